// round 6
// baseline (speedup 1.0000x reference)
#include <cuda_runtime.h>
#include <math.h>

// ------------------------------------------------------------------
// Problem constants
// ------------------------------------------------------------------
#define B_    4
#define C_    256
#define H_    128
#define W_    128
#define HW    (H_*W_)          // 16384
#define NTOK  (B_*HW)          // 65536
#define CB    128
#define HEADS 2
#define CD    64
#define SCALE 0.08838834764831845f
#define EPS   1e-4f

typedef unsigned long long ull;
typedef unsigned int uint32;

// ------------------------------------------------------------------
// f32x2 helpers (attention path)
// ------------------------------------------------------------------
__device__ __forceinline__ ull pk2(float v) {
    ull r; asm("mov.b64 %0, {%1, %1};" : "=l"(r) : "f"(v)); return r;
}
__device__ __forceinline__ void fma2(ull& d, ull a, ull b) {
    asm("fma.rn.f32x2 %0, %1, %2, %0;" : "+l"(d) : "l"(a), "l"(b));
}
__device__ __forceinline__ void add2(ull& d, ull a) {
    asm("add.rn.f32x2 %0, %0, %1;" : "+l"(d) : "l"(a));
}
__device__ __forceinline__ float2 up2(ull v) {
    float2 r; asm("mov.b64 {%0, %1}, %2;" : "=f"(r.x), "=f"(r.y) : "l"(v)); return r;
}
// round-to-nearest tf32 (kept in fp32 container)
__device__ __forceinline__ float tf32r(float v) {
    uint32 r; asm("cvt.rna.tf32.f32 %0, %1;" : "=r"(r) : "f"(v));
    return __uint_as_float(r);
}

// m16n8k8 tf32 mma.sync (target-portable, works on sm_103 non-'a')
__device__ __forceinline__ void mma8(float* d, const uint32* a, const uint32* b) {
    asm volatile("mma.sync.aligned.m16n8k8.row.col.f32.tf32.tf32.f32 "
        "{%0,%1,%2,%3}, {%4,%5,%6,%7}, {%8,%9}, {%0,%1,%2,%3};"
        : "+f"(d[0]), "+f"(d[1]), "+f"(d[2]), "+f"(d[3])
        : "r"(a[0]), "r"(a[1]), "r"(a[2]), "r"(a[3]), "r"(b[0]), "r"(b[1]));
}

// ------------------------------------------------------------------
// Scratch
// ------------------------------------------------------------------
__device__ float g_xnh[(size_t)NTOK * C_];        // LN output hi (tf32)
__device__ float g_xnl[(size_t)NTOK * C_];        // LN output lo (tf32)
__device__ float g_qkv[(size_t)NTOK * 3 * C_];    // [t][ qkv(3) br(2) head(2) d(64) ]
__device__ float g_xc [(size_t)NTOK * C_];        // attn+lepe, [t][c]
__device__ float g_xch[(size_t)NTOK * C_];
__device__ float g_xcl[(size_t)NTOK * C_];
__device__ float g_wqh[768 * 256];                // qkv weight^T hi [n][k]
__device__ float g_wql[768 * 256];
__device__ float g_pwh[256 * 256];                // proj weight hi [o][k]
__device__ float g_pwl[256 * 256];

__device__ __forceinline__ int win_token(int br, int win, int s) {
    int b  = win >> 5;
    int wi = win & 31;
    int y, x;
    if (br == 0) { y = s >> 2;               x = (wi << 2) + (s & 3); }
    else         { y = (wi << 2) + (s >> 7); x = s & 127; }
    return b * HW + y * W_ + x;
}

// ------------------------------------------------------------------
// 1) LayerNorm -> hi/lo tf32 splits
// ------------------------------------------------------------------
__global__ void __launch_bounds__(256) ln_kernel(const float* __restrict__ x,
                                                 const float* __restrict__ gam,
                                                 const float* __restrict__ bet) {
    __shared__ float xs[C_][33];
    __shared__ float mu_s[32], rs_s[32];
    int tid = threadIdx.x;
    int tx = tid & 31, ty = tid >> 5;
    int t0 = blockIdx.x * 32;
    int b  = t0 / HW;
    int pp = t0 - b * HW;
    const float* xb = x + (size_t)b * C_ * HW + pp + tx;
    #pragma unroll
    for (int c = ty; c < C_; c += 8)
        xs[c][tx] = xb[(size_t)c * HW];
    __syncthreads();
    if (tid < 32) {
        float s = 0.f, s2 = 0.f;
        #pragma unroll 8
        for (int c = 0; c < C_; c++) { float v = xs[c][tid]; s += v; s2 += v * v; }
        float mu  = s * (1.0f / C_);
        float var = s2 * (1.0f / C_) - mu * mu;
        mu_s[tid] = mu;
        rs_s[tid] = rsqrtf(var + EPS);
    }
    __syncthreads();
    for (int idx = tid; idx < 32 * C_; idx += 256) {
        int c = idx & 255, tk = idx >> 8;
        float v = (xs[c][tk] - mu_s[tk]) * rs_s[tk] * gam[c] + bet[c];
        float h = tf32r(v);
        size_t o = (size_t)(t0 + tk) * C_ + c;
        g_xnh[o] = h;
        g_xnl[o] = tf32r(v - h);
    }
}

// ------------------------------------------------------------------
// 1b) weight splits (qkv transposed to [n][k]; proj already [o][k])
// ------------------------------------------------------------------
__global__ void __launch_bounds__(256) w_split(const float* __restrict__ wqkv,
                                               const float* __restrict__ projw) {
    int idx = blockIdx.x * 256 + threadIdx.x;
    if (idx < 768 * 256) {
        int n = idx >> 8, k = idx & 255;
        float v = wqkv[(size_t)k * 768 + n];
        float h = tf32r(v);
        g_wqh[idx] = h;
        g_wql[idx] = tf32r(v - h);
    }
    if (idx < 256 * 256) {
        float v = projw[idx];
        float h = tf32r(v);
        g_pwh[idx] = h;
        g_pwl[idx] = tf32r(v - h);
    }
}

// ------------------------------------------------------------------
// 1c) xc hi/lo split (after attention)
// ------------------------------------------------------------------
__global__ void __launch_bounds__(256) xc_split() {
    size_t idx = (size_t)blockIdx.x * 256 + threadIdx.x;   // float4 index
    float4 v = ((const float4*)g_xc)[idx];
    float4 h, l;
    h.x = tf32r(v.x); l.x = tf32r(v.x - h.x);
    h.y = tf32r(v.y); l.y = tf32r(v.y - h.y);
    h.z = tf32r(v.z); l.z = tf32r(v.z - h.z);
    h.w = tf32r(v.w); l.w = tf32r(v.w - h.w);
    ((float4*)g_xch)[idx] = h;
    ((float4*)g_xcl)[idx] = l;
}

// ------------------------------------------------------------------
// mma.sync 3xTF32 GEMM core. Block tile 128x128, K=256 (8 chunks of 32).
// 8 warps: warp_m = wid&1 (64 rows), warp_n = wid>>1 (32 cols).
// SMEM floats: Ah[128][36] @0, Al @4608, Bh @9216, Bl @13824 (18432 fl total)
// D staged afterward in same smem: Ds[128][129].
// ------------------------------------------------------------------
#define ASH 0
#define ASL 4608
#define BSH 9216
#define BSL 13824
#define SMEM_GEMM_BYTES (18432 * 4)

extern __shared__ float sm_g[];

__device__ __forceinline__ void mma_mainloop(
        const float* __restrict__ Ah, const float* __restrict__ Al,
        const float* __restrict__ Bh, const float* __restrict__ Bl,
        int m0, int n0, float acc[4][4][4]) {
    int tid  = threadIdx.x;
    int wid  = tid >> 5, lane = tid & 31;
    int wm   = (wid & 1) * 64;
    int wn   = (wid >> 1) * 32;
    int grp  = lane >> 2, tig = lane & 3;

    for (int ck = 0; ck < 8; ck++) {
        int k0 = ck * 32;
        __syncthreads();
        #pragma unroll
        for (int idx = tid; idx < 1024; idx += 256) {
            int r = idx >> 3, q = (idx & 7) * 4;
            size_t ga = (size_t)(m0 + r) * 256 + k0 + q;
            size_t gb = (size_t)(n0 + r) * 256 + k0 + q;
            int so = r * 36 + q;
            *(float4*)&sm_g[ASH + so] = *(const float4*)(Ah + ga);
            *(float4*)&sm_g[ASL + so] = *(const float4*)(Al + ga);
            *(float4*)&sm_g[BSH + so] = *(const float4*)(Bh + gb);
            *(float4*)&sm_g[BSL + so] = *(const float4*)(Bl + gb);
        }
        __syncthreads();
        #pragma unroll
        for (int ks = 0; ks < 4; ks++) {
            int kk = ks * 8;
            uint32 bh[4][2], bl[4][2];
            #pragma unroll
            for (int j = 0; j < 4; j++) {
                int nb = (wn + j * 8 + grp) * 36 + kk + tig;
                bh[j][0] = __float_as_uint(sm_g[BSH + nb]);
                bh[j][1] = __float_as_uint(sm_g[BSH + nb + 4]);
                bl[j][0] = __float_as_uint(sm_g[BSL + nb]);
                bl[j][1] = __float_as_uint(sm_g[BSL + nb + 4]);
            }
            #pragma unroll
            for (int i = 0; i < 4; i++) {
                int mb = (wm + i * 16 + grp) * 36 + kk + tig;
                uint32 ah[4], al[4];
                ah[0] = __float_as_uint(sm_g[ASH + mb]);
                ah[1] = __float_as_uint(sm_g[ASH + mb + 8 * 36]);
                ah[2] = __float_as_uint(sm_g[ASH + mb + 4]);
                ah[3] = __float_as_uint(sm_g[ASH + mb + 8 * 36 + 4]);
                al[0] = __float_as_uint(sm_g[ASL + mb]);
                al[1] = __float_as_uint(sm_g[ASL + mb + 8 * 36]);
                al[2] = __float_as_uint(sm_g[ASL + mb + 4]);
                al[3] = __float_as_uint(sm_g[ASL + mb + 8 * 36 + 4]);
                #pragma unroll
                for (int j = 0; j < 4; j++) {
                    mma8(acc[i][j], ah, bh[j]);
                    mma8(acc[i][j], ah, bl[j]);
                    mma8(acc[i][j], al, bh[j]);
                }
            }
        }
    }
    // stage D into smem: Ds[128][129]
    __syncthreads();
    #pragma unroll
    for (int i = 0; i < 4; i++)
        #pragma unroll
        for (int j = 0; j < 4; j++) {
            int m = wm + i * 16 + grp;
            int n = wn + j * 8 + tig * 2;
            sm_g[m * 129 + n]             = acc[i][j][0];
            sm_g[m * 129 + n + 1]         = acc[i][j][1];
            sm_g[(m + 8) * 129 + n]       = acc[i][j][2];
            sm_g[(m + 8) * 129 + n + 1]   = acc[i][j][3];
        }
    __syncthreads();
}

// ------------------------------------------------------------------
// 2) QKV GEMM with head-deinterleave permutation
// ------------------------------------------------------------------
__global__ void __launch_bounds__(256) gemm_qkv_mma() {
    float acc[4][4][4] = {};
    int m0 = blockIdx.y * 128;
    int n0 = blockIdx.x * 128;
    mma_mainloop(g_xnh, g_xnl, g_wqh, g_wql, m0, n0, acc);
    int tid = threadIdx.x;
    for (int i = tid; i < 128 * 128; i += 256) {
        int m = i >> 7, n = i & 127;
        int ng = n0 + n;
        int part = ng >> 8, rm = ng & 255;
        int pn = (part << 8) + ((rm >> 7) << 7) + ((rm & 1) << 6) + ((rm & 127) >> 1);
        g_qkv[(size_t)(m0 + m) * 768 + pn] = sm_g[m * 129 + n];
    }
}

// ------------------------------------------------------------------
// 5) Proj GEMM, channel-major output + bias
// ------------------------------------------------------------------
__global__ void __launch_bounds__(256) gemm_proj_mma(const float* __restrict__ Pb,
                                                     float* __restrict__ out) {
    float acc[4][4][4] = {};
    int m0 = blockIdx.y * 128;
    int n0 = blockIdx.x * 128;
    mma_mainloop(g_xch, g_xcl, g_pwh, g_pwl, m0, n0, acc);
    int tid = threadIdx.x;
    int b  = m0 >> 14;
    int pp = m0 & (HW - 1);
    int mm = tid & 127;
    int oh = tid >> 7;          // 0/1
    float* Op = out + (size_t)b * C_ * HW + pp + mm;
    #pragma unroll 4
    for (int oo = 0; oo < 64; oo++) {
        int o = n0 + oh * 64 + oo;
        Op[(size_t)o * HW] = sm_g[mm * 129 + oh * 64 + oo] + Pb[o];
    }
}

// ------------------------------------------------------------------
// 3) LePE depthwise 3x3 per strip window -> g_xc
// ------------------------------------------------------------------
__global__ void lepe_kernel(const float* __restrict__ w1, const float* __restrict__ b1,
                            const float* __restrict__ w2, const float* __restrict__ b2) {
    int cc  = threadIdx.x;
    int s   = blockIdx.x * blockDim.y + threadIdx.y;
    int win = blockIdx.y;
    int br  = blockIdx.z;
    const float* w = (br == 0 ? w1 : w2) + cc * 9;
    float bias = (br == 0 ? b1 : b2)[cc];
    int hsp = (br == 0) ? 128 : 4;
    int wsp = (br == 0) ? 4   : 128;
    int i = s / wsp, j = s % wsp;
    int vcol = 512 + br * 128 + ((cc & 1) << 6) + (cc >> 1);
    float acc = bias;
    #pragma unroll
    for (int ki = 0; ki < 3; ki++) {
        int ii = i + ki - 1;
        if (ii < 0 || ii >= hsp) continue;
        #pragma unroll
        for (int kj = 0; kj < 3; kj++) {
            int jj = j + kj - 1;
            if (jj < 0 || jj >= wsp) continue;
            int tn = win_token(br, win, ii * wsp + jj);
            acc += w[ki * 3 + kj] * g_qkv[(size_t)tn * 768 + vcol];
        }
    }
    int t = win_token(br, win, s);
    g_xc[(size_t)t * C_ + br * 128 + cc] = acc;
}

// ------------------------------------------------------------------
// 4) Attention (f32x2, 512 threads) — passing R3 version
// ------------------------------------------------------------------
#define SSTR 513
#define QSTR 66
#define KSTR 257
#define VSTR 66
extern __shared__ float sm_attn[];
__global__ void __launch_bounds__(512) attn_kernel() {
    float* S   = sm_attn;
    float* Qst = S + 64 * SSTR;
    float* Kt  = Qst + 64 * QSTR;
    float* VA  = Qst;
    float* VB  = VA + 128 * VSTR;
    int qt   = blockIdx.x;
    int head = blockIdx.y;
    int wb   = blockIdx.z;
    int br   = wb >> 7;
    int win  = wb & 127;
    int tid  = threadIdx.x;
    int base = br * 128 + head * 64;

    for (int idx = tid; idx < 64 * 64; idx += 512) {
        int d = idx & 63, r = idx >> 6;
        int t = win_token(br, win, qt * 64 + r);
        Qst[d * QSTR + r] = g_qkv[(size_t)t * 768 + base + d] * SCALE;
    }

    int w    = tid >> 5, lane = tid & 31;
    int r0   = (w & 7) * 8;
    int ch   = w >> 3;

    for (int kc = 0; kc < 2; kc++) {
        __syncthreads();
        for (int idx = tid; idx < 64 * 256; idx += 512) {
            int d = idx & 63, cc = idx >> 6;
            int t = win_token(br, win, kc * 256 + cc);
            Kt[d * KSTR + cc] = g_qkv[(size_t)t * 768 + 256 + base + d];
        }
        __syncthreads();
        ull acc[4][4] = {};
        #pragma unroll 4
        for (int d = 0; d < 64; d++) {
            ull a2[4];
            #pragma unroll
            for (int i = 0; i < 4; i++)
                a2[i] = *(const ull*)&Qst[d * QSTR + r0 + 2 * i];
            #pragma unroll
            for (int j = 0; j < 4; j++) {
                ull b2 = pk2(Kt[d * KSTR + ch * 128 + j * 32 + lane]);
                #pragma unroll
                for (int i = 0; i < 4; i++) fma2(acc[i][j], a2[i], b2);
            }
        }
        #pragma unroll
        for (int i = 0; i < 4; i++)
            #pragma unroll
            for (int j = 0; j < 4; j++) {
                float2 u = up2(acc[i][j]);
                int cc = kc * 256 + ch * 128 + j * 32 + lane;
                S[(r0 + 2 * i) * SSTR + cc]     = u.x;
                S[(r0 + 2 * i + 1) * SSTR + cc] = u.y;
            }
    }
    __syncthreads();

    for (int r = w * 4; r < w * 4 + 4; r++) {
        float* row = S + r * SSTR;
        float m = -1e30f;
        for (int cc = lane; cc < 512; cc += 32) m = fmaxf(m, row[cc]);
        #pragma unroll
        for (int o = 16; o; o >>= 1) m = fmaxf(m, __shfl_xor_sync(0xffffffffu, m, o));
        float ssum = 0.f;
        for (int cc = lane; cc < 512; cc += 32) {
            float e = __expf(row[cc] - m);
            row[cc] = e;
            ssum += e;
        }
        #pragma unroll
        for (int o = 16; o; o >>= 1) ssum += __shfl_xor_sync(0xffffffffu, ssum, o);
        float inv = 1.0f / ssum;
        for (int cc = lane; cc < 512; cc += 32) row[cc] *= inv;
    }

    int b8  = tid & 255;
    int h   = tid >> 8;
    int txd = b8 & 15, tyq = b8 >> 4;
    int rq  = tyq * 4, d0 = txd * 4;
    ull o2[4][2] = {};
    for (int vtp = 0; vtp < 2; vtp++) {
        __syncthreads();
        for (int idx = tid; idx < 2 * 128 * 64; idx += 512) {
            int d = idx & 63, kk = (idx >> 6) & 127;
            int cidx = idx >> 13;
            int t = win_token(br, win, (vtp * 2 + cidx) * 128 + kk);
            float* dst = cidx ? VB : VA;
            dst[kk * VSTR + d] = g_qkv[(size_t)t * 768 + 512 + base + d];
        }
        __syncthreads();
        const float* Vm = h ? VB : VA;
        int koff = (vtp * 2 + h) * 128;
        #pragma unroll 4
        for (int k = 0; k < 128; k++) {
            ull v0 = *(const ull*)&Vm[k * VSTR + d0];
            ull v1 = *(const ull*)&Vm[k * VSTR + d0 + 2];
            #pragma unroll
            for (int i = 0; i < 4; i++) {
                ull p2 = pk2(S[(rq + i) * SSTR + koff + k]);
                fma2(o2[i][0], p2, v0);
                fma2(o2[i][1], p2, v1);
            }
        }
    }

    ull* red = (ull*)S;
    __syncthreads();
    if (h == 1) {
        #pragma unroll
        for (int i = 0; i < 4; i++) {
            red[b8 * 8 + 2 * i]     = o2[i][0];
            red[b8 * 8 + 2 * i + 1] = o2[i][1];
        }
    }
    __syncthreads();
    if (h == 0) {
        #pragma unroll
        for (int i = 0; i < 4; i++) {
            add2(o2[i][0], red[b8 * 8 + 2 * i]);
            add2(o2[i][1], red[b8 * 8 + 2 * i + 1]);
        }
        #pragma unroll
        for (int i = 0; i < 4; i++) {
            int t = win_token(br, win, qt * 64 + rq + i);
            size_t gb = (size_t)t * C_ + br * 128 + head;
            #pragma unroll
            for (int jp = 0; jp < 2; jp++) {
                float2 u = up2(o2[i][jp]);
                g_xc[gb + 2 * (d0 + 2 * jp)]     += u.x;
                g_xc[gb + 2 * (d0 + 2 * jp + 1)] += u.y;
            }
        }
    }
}

// ------------------------------------------------------------------
// launch
// ------------------------------------------------------------------
extern "C" void kernel_launch(void* const* d_in, const int* in_sizes, int n_in,
                              void* d_out, int out_size) {
    const float* x       = (const float*)d_in[0];
    const float* ln_g    = (const float*)d_in[1];
    const float* ln_b    = (const float*)d_in[2];
    const float* w_qkv   = (const float*)d_in[3];
    const float* lepe_w1 = (const float*)d_in[4];
    const float* lepe_b1 = (const float*)d_in[5];
    const float* lepe_w2 = (const float*)d_in[6];
    const float* lepe_b2 = (const float*)d_in[7];
    const float* proj_w  = (const float*)d_in[8];
    const float* proj_b  = (const float*)d_in[9];
    float* out = (float*)d_out;

    size_t smem_attn = (size_t)(64 * SSTR + 64 * QSTR + 64 * KSTR) * sizeof(float);
    cudaFuncSetAttribute(attn_kernel, cudaFuncAttributeMaxDynamicSharedMemorySize,
                         (int)smem_attn);
    cudaFuncSetAttribute(gemm_qkv_mma,  cudaFuncAttributeMaxDynamicSharedMemorySize, SMEM_GEMM_BYTES);
    cudaFuncSetAttribute(gemm_proj_mma, cudaFuncAttributeMaxDynamicSharedMemorySize, SMEM_GEMM_BYTES);

    ln_kernel  <<< NTOK / 32, 256 >>>(x, ln_g, ln_b);
    w_split    <<< 768, 256 >>>(w_qkv, proj_w);
    gemm_qkv_mma <<< dim3(6, 512), 256, SMEM_GEMM_BYTES >>>();
    lepe_kernel <<< dim3(128, 128, 2), dim3(128, 4) >>>(lepe_w1, lepe_b1, lepe_w2, lepe_b2);
    attn_kernel <<< dim3(8, 2, 256), 512, smem_attn >>>();
    xc_split   <<< (NTOK * C_ / 4) / 256, 256 >>>();
    gemm_proj_mma <<< dim3(2, 512), 256, SMEM_GEMM_BYTES >>>(proj_b, out);
}